// round 17
// baseline (speedup 1.0000x reference)
#include <cuda_runtime.h>
#include <cstddef>

// ---------------------------------------------------------------------------
// DRTScorer: out[b,p] = sum_k alpha[b,k] * <qhat[b,k,:], dhat[p,k,:]>
// B=64, P=100000, E=384, H=512, K=6, SUB=64  (all fp32)
//
// Pipeline (4 launches):
//   1) query_kernel: Qw[b, k*64+u] = alpha[b,k] * qhat[b,k,u]      (64 x 384)
//   2) H = relu(doc @ W1 + b1)                  f32x2 GEMM          (P x 512)
//   3) S = normalize_chunks(H @ W2 + b2)        f32x2 GEMM + fused  (P x 384)
//   4) out = Qw @ S^T                           f32x2 GEMM          (64 x P)
//
// All big GEMM inner loops use Blackwell packed fma.rn.f32x2 (2x FLOP/instr;
// ptxas never emits FFMA2 from scalar C++). A-tiles are stored pre-duplicated
// as 64-bit (v,v) pairs in shared so FMA2 operands come straight from LDS.128.
// ---------------------------------------------------------------------------

#define MAX_P 100000
#define MAX_B 64

typedef unsigned long long u64;

// scratch (device globals -- allocation-free per harness rules)
__device__ __align__(16) static float g_H [(size_t)MAX_P * 512];
__device__ __align__(16) static float g_S [(size_t)MAX_P * 384];
__device__ __align__(16) static float g_Qw[(size_t)MAX_B * 384];

// ---- packed f32x2 helpers --------------------------------------------------
__device__ __forceinline__ u64 dup_f32(float v) {
    u64 r; asm("mov.b64 %0, {%1, %1};" : "=l"(r) : "f"(v)); return r;
}
__device__ __forceinline__ void fma2(u64& d, u64 a, u64 b) {
    asm("fma.rn.f32x2 %0, %1, %2, %3;" : "=l"(d) : "l"(a), "l"(b), "l"(d));
}
__device__ __forceinline__ float2 unpk(u64 u) {
    float lo, hi; asm("mov.b64 {%0, %1}, %2;" : "=f"(lo), "=f"(hi) : "l"(u));
    return make_float2(lo, hi);
}

// ---------------------------------------------------------------------------
// Kernel 1: per-query encode + alphas, folded into Qw.  One block per query.
// ---------------------------------------------------------------------------
__global__ __launch_bounds__(512)
void query_kernel(const float* __restrict__ q_emb,
                  const float* __restrict__ W1,  const float* __restrict__ b1,
                  const float* __restrict__ W2,  const float* __restrict__ b2,
                  const float* __restrict__ Wa1, const float* __restrict__ ba1,
                  const float* __restrict__ Wa2, const float* __restrict__ ba2,
                  float* __restrict__ Qw)
{
    __shared__ float q[384];
    __shared__ float h[512];
    __shared__ float s[384];
    __shared__ float ha[64];
    __shared__ float lg[6];
    __shared__ float alpha[6];
    __shared__ float csum[6];

    const int b = blockIdx.x;
    const int t = threadIdx.x;

    if (t < 384) q[t] = q_emb[(size_t)b * 384 + t];
    __syncthreads();

    {
        float acc = b1[t];
        #pragma unroll 8
        for (int e = 0; e < 384; e++) acc = fmaf(q[e], W1[(size_t)e * 512 + t], acc);
        h[t] = fmaxf(acc, 0.0f);
    }
    __syncthreads();

    if (t < 384) {
        float acc = b2[t];
        #pragma unroll 8
        for (int e = 0; e < 512; e++) acc = fmaf(h[e], W2[(size_t)e * 384 + t], acc);
        s[t] = acc;
    } else if (t < 448) {
        const int j = t - 384;
        float acc = ba1[j];
        #pragma unroll 8
        for (int e = 0; e < 384; e++) acc = fmaf(q[e], Wa1[(size_t)e * 64 + j], acc);
        ha[j] = fmaxf(acc, 0.0f);
    }
    __syncthreads();

    if (t < 6) {
        float acc = ba2[t];
        #pragma unroll 8
        for (int e = 0; e < 64; e++) acc = fmaf(ha[e], Wa2[(size_t)e * 6 + t], acc);
        lg[t] = acc;

        float ss = 0.0f;
        #pragma unroll 8
        for (int j = 0; j < 64; j++) { float v = s[t * 64 + j]; ss = fmaf(v, v, ss); }
        csum[t] = ss;
    }
    __syncthreads();

    if (t == 0) {
        float m = lg[0];
        #pragma unroll
        for (int i = 1; i < 6; i++) m = fmaxf(m, lg[i]);
        float e[6], sum = 0.0f;
        #pragma unroll
        for (int i = 0; i < 6; i++) { e[i] = expf(lg[i] - m); sum += e[i]; }
        #pragma unroll
        for (int i = 0; i < 6; i++) alpha[i] = e[i] / sum;
    }
    __syncthreads();

    if (t < 384) {
        const int c = t >> 6;
        const float inv = alpha[c] * rsqrtf(csum[c] + 1e-12f);
        Qw[(size_t)b * 384 + t] = s[t] * inv;
    }
}

// ---------------------------------------------------------------------------
// Kernels 2/3: SGEMM  C[M,N] = op(A[M,K] @ B[K,N] + bias[N])
//   RELU: elementwise relu.  NORM: per-row per-64-col-chunk L2 normalize
//   (chunk fits inside the 128-col tile; 8-lane shfl reduce).
// BM=128, BN=128, BK=16, 256 threads, 8x8 per thread via 8x4 fma.rn.f32x2.
// K and N are exact multiples of BK/BN; only M is ragged.
// ---------------------------------------------------------------------------
template <bool RELU, bool NORM>
__global__ __launch_bounds__(256, 2)
void sgemm_f32x2(const float* __restrict__ A, const float* __restrict__ B,
                 const float* __restrict__ bias, float* __restrict__ C,
                 int M, int N, int K)
{
    constexpr int BM = 128, BN = 128, BK = 16;
    __shared__ __align__(16) u64   Asd[BK][BM + 2];  // A tile, each value dup'd (v,v)
    __shared__ __align__(16) float Bs [BK][BN];

    const int tid = threadIdx.x;
    const int tx = tid & 15;           // 0..15 -> N
    const int ty = tid >> 4;           // 0..15 -> M
    const int rowBase = blockIdx.y * BM;
    const int colBase = blockIdx.x * BN;

    const int arow0 = tid >> 2;        // 0..63
    const int acg   = (tid & 3) * 4;   // k sub-offset
    const int brow0 = tid >> 5;        // 0..7
    const int bcol  = (tid & 31) * 4;

    u64 acc[8][4];
    #pragma unroll
    for (int i = 0; i < 8; i++)
        #pragma unroll
        for (int j = 0; j < 4; j++) acc[i][j] = 0ull;

    for (int k0 = 0; k0 < K; k0 += BK) {
        #pragma unroll
        for (int i = 0; i < 2; i++) {
            const int r  = arow0 + i * 64;
            int gr = rowBase + r; if (gr >= M) gr = M - 1;  // clamp; store is guarded
            const float4 f = *reinterpret_cast<const float4*>(&A[(size_t)gr * K + k0 + acg]);
            Asd[acg + 0][r] = dup_f32(f.x); Asd[acg + 1][r] = dup_f32(f.y);
            Asd[acg + 2][r] = dup_f32(f.z); Asd[acg + 3][r] = dup_f32(f.w);
        }
        #pragma unroll
        for (int i = 0; i < 2; i++) {
            const int r = brow0 + i * 8;
            const float4 f = *reinterpret_cast<const float4*>(&B[(size_t)(k0 + r) * N + colBase + bcol]);
            *reinterpret_cast<float4*>(&Bs[r][bcol]) = f;
        }
        __syncthreads();

        #pragma unroll
        for (int k = 0; k < BK; k++) {
            const ulonglong2 a01 = *reinterpret_cast<const ulonglong2*>(&Asd[k][ty * 8 + 0]);
            const ulonglong2 a23 = *reinterpret_cast<const ulonglong2*>(&Asd[k][ty * 8 + 2]);
            const ulonglong2 a45 = *reinterpret_cast<const ulonglong2*>(&Asd[k][ty * 8 + 4]);
            const ulonglong2 a67 = *reinterpret_cast<const ulonglong2*>(&Asd[k][ty * 8 + 6]);
            const ulonglong2 bL  = *reinterpret_cast<const ulonglong2*>(&Bs[k][tx * 8 + 0]);
            const ulonglong2 bH  = *reinterpret_cast<const ulonglong2*>(&Bs[k][tx * 8 + 4]);
            const u64 a2[8] = {a01.x, a01.y, a23.x, a23.y, a45.x, a45.y, a67.x, a67.y};
            const u64 b2[4] = {bL.x, bL.y, bH.x, bH.y};
            #pragma unroll
            for (int i = 0; i < 8; i++)
                #pragma unroll
                for (int jp = 0; jp < 4; jp++)
                    fma2(acc[i][jp], a2[i], b2[jp]);
        }
        __syncthreads();
    }

    // epilogue: bias (+relu | +chunk-normalize), predicated store on M.
    float bv[8];
    #pragma unroll
    for (int j = 0; j < 8; j++) bv[j] = bias[colBase + tx * 8 + j];

    #pragma unroll
    for (int i = 0; i < 8; i++) {
        const int gr = rowBase + ty * 8 + i;
        float v[8];
        #pragma unroll
        for (int jp = 0; jp < 4; jp++) {
            const float2 p = unpk(acc[i][jp]);
            v[2 * jp]     = p.x + bv[2 * jp];
            v[2 * jp + 1] = p.y + bv[2 * jp + 1];
        }
        if (RELU) {
            #pragma unroll
            for (int j = 0; j < 8; j++) v[j] = fmaxf(v[j], 0.0f);
        }
        if (NORM) {
            // 64-col chunk = 8 lanes with same ty, same (tx>>3); those lanes are
            // an aligned 8-lane group within the warp, so xor-shuffles 4/2/1 reduce.
            float ss = 0.0f;
            #pragma unroll
            for (int j = 0; j < 8; j++) ss = fmaf(v[j], v[j], ss);
            ss += __shfl_xor_sync(0xffffffffu, ss, 4);
            ss += __shfl_xor_sync(0xffffffffu, ss, 2);
            ss += __shfl_xor_sync(0xffffffffu, ss, 1);
            const float inv = rsqrtf(ss + 1e-12f);
            #pragma unroll
            for (int j = 0; j < 8; j++) v[j] *= inv;
        }
        if (gr < M) {
            const int gc = colBase + tx * 8;
            *reinterpret_cast<float4*>(&C[(size_t)gr * N + gc])     = make_float4(v[0], v[1], v[2], v[3]);
            *reinterpret_cast<float4*>(&C[(size_t)gr * N + gc + 4]) = make_float4(v[4], v[5], v[6], v[7]);
        }
    }
}

// ---------------------------------------------------------------------------
// Kernel 4: out[64, P] = Qw[64, 384] @ S^T.  Tile 64 x 256, BK=16, 256 thr,
// 8(b) x 8(p) per thread via f32x2.
// ---------------------------------------------------------------------------
__global__ __launch_bounds__(256, 2)
void score_kernel(const float* __restrict__ Qw, const float* __restrict__ S,
                  float* __restrict__ out, int P)
{
    constexpr int BN = 256, BK = 16;
    __shared__ __align__(16) u64   Qsd[BK][64 + 2];   // dup'd Qw tile
    __shared__ __align__(16) float Ss [BK][BN + 4];

    const int tid = threadIdx.x;
    const int tx = tid & 31;   // 0..31 -> p
    const int ty = tid >> 5;   // 0..7  -> b
    const int pBase = blockIdx.x * BN;

    const int qr  = tid >> 2;          // 0..63
    const int qcg = (tid & 3) * 4;

    u64 acc[8][4];
    #pragma unroll
    for (int i = 0; i < 8; i++)
        #pragma unroll
        for (int j = 0; j < 4; j++) acc[i][j] = 0ull;

    for (int k0 = 0; k0 < 384; k0 += BK) {
        {
            const float4 f = *reinterpret_cast<const float4*>(&Qw[(size_t)qr * 384 + k0 + qcg]);
            Qsd[qcg + 0][qr] = dup_f32(f.x); Qsd[qcg + 1][qr] = dup_f32(f.y);
            Qsd[qcg + 2][qr] = dup_f32(f.z); Qsd[qcg + 3][qr] = dup_f32(f.w);
        }
        #pragma unroll
        for (int i = 0; i < 4; i++) {
            const int idx = tid + i * 256;
            const int p   = idx >> 2;          // 0..255
            const int cg  = (idx & 3) * 4;
            int gp = pBase + p; if (gp >= P) gp = P - 1;
            const float4 f = *reinterpret_cast<const float4*>(&S[(size_t)gp * 384 + k0 + cg]);
            Ss[cg + 0][p] = f.x; Ss[cg + 1][p] = f.y;
            Ss[cg + 2][p] = f.z; Ss[cg + 3][p] = f.w;
        }
        __syncthreads();

        #pragma unroll
        for (int k = 0; k < BK; k++) {
            const ulonglong2 a01 = *reinterpret_cast<const ulonglong2*>(&Qsd[k][ty * 8 + 0]);
            const ulonglong2 a23 = *reinterpret_cast<const ulonglong2*>(&Qsd[k][ty * 8 + 2]);
            const ulonglong2 a45 = *reinterpret_cast<const ulonglong2*>(&Qsd[k][ty * 8 + 4]);
            const ulonglong2 a67 = *reinterpret_cast<const ulonglong2*>(&Qsd[k][ty * 8 + 6]);
            const ulonglong2 bL  = *reinterpret_cast<const ulonglong2*>(&Ss[k][tx * 8 + 0]);
            const ulonglong2 bH  = *reinterpret_cast<const ulonglong2*>(&Ss[k][tx * 8 + 4]);
            const u64 a2[8] = {a01.x, a01.y, a23.x, a23.y, a45.x, a45.y, a67.x, a67.y};
            const u64 b2[4] = {bL.x, bL.y, bH.x, bH.y};
            #pragma unroll
            for (int i = 0; i < 8; i++)
                #pragma unroll
                for (int jp = 0; jp < 4; jp++)
                    fma2(acc[i][jp], a2[i], b2[jp]);
        }
        __syncthreads();
    }

    // epilogue: P is a multiple of 8, so float4 granularity is safe when gp < P.
    #pragma unroll
    for (int i = 0; i < 8; i++) {
        const int b = ty * 8 + i;
        const int gp = pBase + tx * 8;
        float v[8];
        #pragma unroll
        for (int jp = 0; jp < 4; jp++) {
            const float2 p = unpk(acc[i][jp]);
            v[2 * jp] = p.x; v[2 * jp + 1] = p.y;
        }
        if (gp < P) {
            *reinterpret_cast<float4*>(&out[(size_t)b * P + gp])     = make_float4(v[0], v[1], v[2], v[3]);
            *reinterpret_cast<float4*>(&out[(size_t)b * P + gp + 4]) = make_float4(v[4], v[5], v[6], v[7]);
        }
    }
}

// ---------------------------------------------------------------------------
// launch
// ---------------------------------------------------------------------------
extern "C" void kernel_launch(void* const* d_in, const int* in_sizes, int n_in,
                              void* d_out, int out_size)
{
    const float* q_emb = (const float*)d_in[0];
    const float* doc   = (const float*)d_in[1];
    const float* W1    = (const float*)d_in[2];
    const float* b1    = (const float*)d_in[3];
    const float* W2    = (const float*)d_in[4];
    const float* b2    = (const float*)d_in[5];
    const float* Wa1   = (const float*)d_in[6];
    const float* ba1   = (const float*)d_in[7];
    const float* Wa2   = (const float*)d_in[8];
    const float* ba2   = (const float*)d_in[9];
    float* out = (float*)d_out;

    const int B = in_sizes[0] / 384;   // 64
    const int P = in_sizes[1] / 384;   // 100000

    float *dH, *dS, *dQw;
    cudaGetSymbolAddress((void**)&dH,  g_H);
    cudaGetSymbolAddress((void**)&dS,  g_S);
    cudaGetSymbolAddress((void**)&dQw, g_Qw);

    // 1) queries -> Qw
    query_kernel<<<B, 512>>>(q_emb, W1, b1, W2, b2, Wa1, ba1, Wa2, ba2, dQw);

    // 2) H = relu(doc @ W1 + b1)    (P x 512, K = 384)
    {
        dim3 grid(512 / 128, (P + 127) / 128);
        sgemm_f32x2<true, false><<<grid, 256>>>(doc, W1, b1, dH, P, 512, 384);
    }

    // 3) S = chunk_normalize(H @ W2 + b2)    (P x 384, K = 512), fused norm
    {
        dim3 grid(384 / 128, (P + 127) / 128);
        sgemm_f32x2<false, true><<<grid, 256>>>(dH, W2, b2, dS, P, 384, 512);
    }

    // 4) out = Qw @ S^T
    score_kernel<<<(P + 255) / 256, 256>>>(dQw, dS, out, P);
}